// round 1
// baseline (speedup 1.0000x reference)
#include <cuda_runtime.h>

namespace {

constexpr int T  = 4096;
constexpr int H  = 16;
constexpr int P  = 64;    // d_head
constexpr int N  = 128;   // d_state
constexpr int L  = 64;    // block_len (last chunk)
constexpr int T0 = T - L; // 4032

__global__ __launch_bounds__(256, 1)
void mamba_final_state_kernel(const float* __restrict__ X,
                              const float* __restrict__ A,
                              const float* __restrict__ Bm,
                              float* __restrict__ out) {
    const int bh    = blockIdx.x;      // 0..31  (b*16 + h)
    const int b     = bh >> 4;
    const int h     = bh & 15;
    const int ntile = blockIdx.y;      // 0..3, 32 n-columns each
    const int tid   = threadIdx.x;     // 256 threads

    __shared__ float a_s[L];
    __shared__ float w[L];
    __shared__ float Xw[L][P];         // 16 KB, w-scaled X
    __shared__ float Bs[L][32];        // 8 KB

    // --- load A for last chunk ---
    if (tid < L)
        a_s[tid] = A[(size_t)(b * T + T0 + tid) * H + h];

    // --- load B tile (independent of w): 64 rows x 32 cols = 512 float4 ---
    {
        const float* bbase = Bm + (size_t)(b * T + T0) * (H * N)
                                + (size_t)h * N + ntile * 32;
        #pragma unroll
        for (int it = 0; it < 2; it++) {
            int i  = tid + it * 256;   // 0..511
            int l  = i >> 3;           // 8 float4 per row
            int c4 = i & 7;
            float4 v = *reinterpret_cast<const float4*>(
                bbase + (size_t)l * (H * N) + c4 * 4);
            *reinterpret_cast<float4*>(&Bs[l][c4 * 4]) = v;
        }
    }
    __syncthreads();

    // --- weights: w[l] = exp(2*S - cumsum_incl[l]) over last chunk ---
    if (tid < L) {
        float c = 0.f, S = 0.f;
        #pragma unroll
        for (int k = 0; k < L; k++) {
            float a = a_s[k];
            S += a;
            if (k <= tid) c += a;
        }
        w[tid] = __expf(2.f * S - c);
    }
    __syncthreads();

    // --- load X and pre-scale by w: 64x64 = 1024 float4 ---
    {
        const float* xbase = X + (size_t)(b * T + T0) * (H * P) + (size_t)h * P;
        #pragma unroll
        for (int it = 0; it < 4; it++) {
            int i  = tid + it * 256;   // 0..1023
            int l  = i >> 4;           // 16 float4 per row
            int c4 = i & 15;
            float4 v = *reinterpret_cast<const float4*>(
                xbase + (size_t)l * (H * P) + c4 * 4);
            float wl = w[l];
            v.x *= wl; v.y *= wl; v.z *= wl; v.w *= wl;
            *reinterpret_cast<float4*>(&Xw[l][c4 * 4]) = v;
        }
    }
    __syncthreads();

    // --- compute: each thread -> (p, 8 consecutive n), K = 64 ---
    const int p  = tid & 63;
    const int ng = tid >> 6;           // 0..3
    float acc[8] = {0.f, 0.f, 0.f, 0.f, 0.f, 0.f, 0.f, 0.f};

    #pragma unroll 8
    for (int l = 0; l < L; l++) {
        float  xv = Xw[l][p];                                         // conflict-free
        float4 b0 = *reinterpret_cast<const float4*>(&Bs[l][ng * 8]);     // broadcast
        float4 b1 = *reinterpret_cast<const float4*>(&Bs[l][ng * 8 + 4]); // broadcast
        acc[0] += xv * b0.x; acc[1] += xv * b0.y;
        acc[2] += xv * b0.z; acc[3] += xv * b0.w;
        acc[4] += xv * b1.x; acc[5] += xv * b1.y;
        acc[6] += xv * b1.z; acc[7] += xv * b1.w;
    }

    float* o = out + ((size_t)(bh * P + p)) * N + ntile * 32 + ng * 8;
    *reinterpret_cast<float4*>(o)     = make_float4(acc[0], acc[1], acc[2], acc[3]);
    *reinterpret_cast<float4*>(o + 4) = make_float4(acc[4], acc[5], acc[6], acc[7]);
}

} // namespace

extern "C" void kernel_launch(void* const* d_in, const int* in_sizes, int n_in,
                              void* d_out, int out_size) {
    const float* X = (const float*)d_in[0];  // (2, 4096, 16, 64)  f32
    const float* A = (const float*)d_in[1];  // (2, 4096, 16)      f32
    const float* B = (const float*)d_in[2];  // (2, 4096, 16, 128) f32
    float* out = (float*)d_out;              // (2, 16, 64, 128)   f32

    dim3 grid(32, 4);   // (b*h pairs, n-tiles of 32)
    mamba_final_state_kernel<<<grid, 256>>>(X, A, B, out);
}

// round 5
// speedup vs baseline: 1.3544x; 1.3544x over previous
#include <cuda_runtime.h>

namespace {

constexpr int T  = 4096;
constexpr int H  = 16;
constexpr int P  = 64;    // d_head
constexpr int N  = 128;   // d_state
constexpr int L  = 64;    // block_len (last chunk)
constexpr int T0 = T - L; // 4032

__device__ __forceinline__ void fma2(unsigned long long& d,
                                     unsigned long long a,
                                     unsigned long long b) {
    asm("fma.rn.f32x2 %0, %1, %2, %0;" : "+l"(d) : "l"(a), "l"(b));
}

__global__ __launch_bounds__(256, 1)
void mamba_final_state_kernel(const float* __restrict__ X,
                              const float* __restrict__ A,
                              const float* __restrict__ Bm,
                              float* __restrict__ out) {
    const int bh    = blockIdx.x;      // 0..31  (b*16 + h)
    const int b     = bh >> 4;
    const int h     = bh & 15;
    const int ntile = blockIdx.y;      // 0..3, 32 n-columns each
    const int tid   = threadIdx.x;     // 256 threads

    __shared__ float Xs[L][P];         // 16 KB, raw X
    __shared__ float Bs[L][32];        // 8 KB, later scaled by w[l]
    __shared__ float wpart[L];         // per-thread scan partials
    __shared__ float wtot[2];          // warp totals
    __shared__ float wsh[L];           // final weights

    // ---- issue ALL gmem loads up front (no dependency between them) ----

    // A for last chunk -> registers of threads 0..63
    float a = 0.f;
    if (tid < L)
        a = A[(size_t)(b * T + T0 + tid) * H + h];

    // X tile raw: 64x64 = 1024 float4
    {
        const float* xbase = X + (size_t)(b * T + T0) * (H * P) + (size_t)h * P;
        #pragma unroll
        for (int it = 0; it < 4; it++) {
            int i  = tid + it * 256;   // 0..1023
            int l  = i >> 4;           // 16 float4 per row
            int c4 = i & 15;
            float4 v = *reinterpret_cast<const float4*>(
                xbase + (size_t)l * (H * P) + c4 * 4);
            *reinterpret_cast<float4*>(&Xs[l][c4 * 4]) = v;
        }
    }

    // B tile raw: 64x32 = 512 float4
    {
        const float* bbase = Bm + (size_t)(b * T + T0) * (H * N)
                                + (size_t)h * N + ntile * 32;
        #pragma unroll
        for (int it = 0; it < 2; it++) {
            int i  = tid + it * 256;   // 0..511
            int l  = i >> 3;           // 8 float4 per row
            int c4 = i & 7;
            float4 v = *reinterpret_cast<const float4*>(
                bbase + (size_t)l * (H * N) + c4 * 4);
            *reinterpret_cast<float4*>(&Bs[l][c4 * 4]) = v;
        }
    }

    // ---- warp-shfl inclusive scan of A (overlaps with X/B loads) ----
    if (tid < L) {
        float c = a;
        #pragma unroll
        for (int off = 1; off < 32; off <<= 1) {
            float t = __shfl_up_sync(0xffffffffu, c, off);
            if ((tid & 31) >= off) c += t;
        }
        wpart[tid] = c;
        if ((tid & 31) == 31) wtot[tid >> 5] = c;
    }
    __syncthreads();

    // ---- finalize weights: w[l] = exp(2*S - cumsum_incl[l]) ----
    if (tid < L) {
        float tot0 = wtot[0];
        float S    = tot0 + wtot[1];
        float cc   = wpart[tid] + (tid >= 32 ? tot0 : 0.f);
        wsh[tid]   = __expf(2.f * S - cc);
    }
    __syncthreads();

    // ---- fold w into B: scale each B row in place (512 float4) ----
    {
        #pragma unroll
        for (int it = 0; it < 2; it++) {
            int i   = tid + it * 256;
            int l   = i >> 3;
            int c4  = i & 7;
            float wl = wsh[l];
            float4 v = *reinterpret_cast<float4*>(&Bs[l][c4 * 4]);
            v.x *= wl; v.y *= wl; v.z *= wl; v.w *= wl;
            *reinterpret_cast<float4*>(&Bs[l][c4 * 4]) = v;
        }
    }
    __syncthreads();

    // ---- compute: thread -> (p, 8 consecutive n) with packed f32x2 FMA ----
    const int p  = tid & 63;
    const int ng = tid >> 6;           // 0..3

    unsigned long long acc0 = 0ull, acc1 = 0ull, acc2 = 0ull, acc3 = 0ull;

    #pragma unroll
    for (int l = 0; l < L; l++) {
        float xv = Xs[l][p];                          // conflict-free LDS
        unsigned long long x2;
        asm("mov.b64 %0, {%1, %1};" : "=l"(x2) : "f"(xv));
        const ulonglong2* bp =
            reinterpret_cast<const ulonglong2*>(&Bs[l][ng * 8]);  // 32B aligned
        ulonglong2 q0 = bp[0];                        // LDS.128 (broadcast)
        ulonglong2 q1 = bp[1];                        // LDS.128 (broadcast)
        fma2(acc0, x2, q0.x);
        fma2(acc1, x2, q0.y);
        fma2(acc2, x2, q1.x);
        fma2(acc3, x2, q1.y);
    }

    float* o = out + ((size_t)(bh * P + p)) * N + ntile * 32 + ng * 8;
    ulonglong2 s0; s0.x = acc0; s0.y = acc1;
    ulonglong2 s1; s1.x = acc2; s1.y = acc3;
    *reinterpret_cast<ulonglong2*>(o)     = s0;       // STG.128
    *reinterpret_cast<ulonglong2*>(o + 4) = s1;       // STG.128
}

} // namespace

extern "C" void kernel_launch(void* const* d_in, const int* in_sizes, int n_in,
                              void* d_out, int out_size) {
    const float* X = (const float*)d_in[0];  // (2, 4096, 16, 64)  f32
    const float* A = (const float*)d_in[1];  // (2, 4096, 16)      f32
    const float* B = (const float*)d_in[2];  // (2, 4096, 16, 128) f32
    float* out = (float*)d_out;              // (2, 16, 64, 128)   f32

    dim3 grid(32, 4);   // (b*h pairs, n-tiles of 32)
    mamba_final_state_kernel<<<grid, 256>>>(X, A, B, out);
}